// round 15
// baseline (speedup 1.0000x reference)
#include <cuda_runtime.h>
#include <cuda_fp16.h>
#include <cstdint>

#define BB 4
#define C 512
#define D 64
#define HW 4096
#define GROUPS 32
#define CPG 16
#define EPS 1e-5f

// Scratch (device globals — no allocation allowed)
__device__ float g_scale[BB * C];
__device__ float g_bias[BB * C];
__device__ __half g_xh[BB * HW * C];     // normalized x, transposed [B,N,C] fp16
__device__ __half g_wqh[D * C], g_wkh[D * C], g_wvh[D * C], g_woh[C * D];
__device__ __half g_qh[BB * HW * D];     // [B,N,D] fp16, pre-scaled by 0.125*log2e
__device__ __half g_kh[BB * HW * D];     // [B,N,D] fp16
__device__ __half g_vth[BB * D * HW];    // [B,D,N] fp16

// ---------------------------------------------------------------------------
// helpers
// ---------------------------------------------------------------------------
__device__ __forceinline__ uint32_t smem_u32(const void* p) {
    uint32_t a;
    asm("{ .reg .u64 t; cvta.to.shared.u64 t, %1; cvt.u32.u64 %0, t; }" : "=r"(a) : "l"(p));
    return a;
}
__device__ __forceinline__ void cp16(uint32_t s, const void* g) {
    asm volatile("cp.async.cg.shared.global [%0], [%1], 16;" :: "r"(s), "l"(g));
}
__device__ __forceinline__ void cp_commit() { asm volatile("cp.async.commit_group;"); }
__device__ __forceinline__ void cp_wait0() { asm volatile("cp.async.wait_group 0;" ::: "memory"); }

__device__ __forceinline__ void mma_f16(float& d0, float& d1, float& d2, float& d3,
                                        uint32_t a0, uint32_t a1, uint32_t a2, uint32_t a3,
                                        uint32_t b0, uint32_t b1,
                                        float c0, float c1, float c2, float c3) {
    asm volatile(
        "mma.sync.aligned.m16n8k16.row.col.f32.f16.f16.f32 "
        "{%0,%1,%2,%3},{%4,%5,%6,%7},{%8,%9},{%10,%11,%12,%13};"
        : "=f"(d0), "=f"(d1), "=f"(d2), "=f"(d3)
        : "r"(a0), "r"(a1), "r"(a2), "r"(a3), "r"(b0), "r"(b1),
          "f"(c0), "f"(c1), "f"(c2), "f"(c3));
}
__device__ __forceinline__ void mma_f16h(uint32_t& d0, uint32_t& d1,
                                         uint32_t a0, uint32_t a1, uint32_t a2, uint32_t a3,
                                         uint32_t b0, uint32_t b1) {
    asm volatile(
        "mma.sync.aligned.m16n8k16.row.col.f16.f16.f16.f16 "
        "{%0,%1},{%2,%3,%4,%5},{%6,%7},{%0,%1};"
        : "+r"(d0), "+r"(d1)
        : "r"(a0), "r"(a1), "r"(a2), "r"(a3), "r"(b0), "r"(b1));
}
__device__ __forceinline__ void ldsm4(uint32_t& r0, uint32_t& r1, uint32_t& r2, uint32_t& r3,
                                      uint32_t addr) {
    asm volatile("ldmatrix.sync.aligned.m8n8.x4.shared.b16 {%0,%1,%2,%3}, [%4];"
                 : "=r"(r0), "=r"(r1), "=r"(r2), "=r"(r3) : "r"(addr));
}
__device__ __forceinline__ uint32_t packh2(float lo, float hi) {
    __half2 h = __floats2half2_rn(lo, hi);
    return *(uint32_t*)&h;
}
__device__ __forceinline__ uint32_t ex2h2(uint32_t s) {
    uint32_t p;
    asm("ex2.approx.f16x2 %0, %1;" : "=r"(p) : "r"(s));
    return p;
}

// ---------------------------------------------------------------------------
// 1a. GroupNorm stats (+ weight convert in 8 extra blocks).
// ---------------------------------------------------------------------------
__global__ void __launch_bounds__(1024) gn_stats_kernel(
        const float* __restrict__ x,
        const float* __restrict__ gamma, const float* __restrict__ beta,
        const float* __restrict__ wq, const float* __restrict__ wk,
        const float* __restrict__ wv, const float* __restrict__ wo) {
    int tid = threadIdx.x;
    if (blockIdx.x >= BB * GROUPS) {
        int id = ((blockIdx.x - BB * GROUPS) * 1024 + tid) * 4;
        float4 a;
        a = *(const float4*)&wq[id];
        *(__half2*)&g_wqh[id] = __floats2half2_rn(a.x, a.y);
        *(__half2*)&g_wqh[id + 2] = __floats2half2_rn(a.z, a.w);
        a = *(const float4*)&wk[id];
        *(__half2*)&g_wkh[id] = __floats2half2_rn(a.x, a.y);
        *(__half2*)&g_wkh[id + 2] = __floats2half2_rn(a.z, a.w);
        a = *(const float4*)&wv[id];
        *(__half2*)&g_wvh[id] = __floats2half2_rn(a.x, a.y);
        *(__half2*)&g_wvh[id + 2] = __floats2half2_rn(a.z, a.w);
        a = *(const float4*)&wo[id];
        *(__half2*)&g_woh[id] = __floats2half2_rn(a.x, a.y);
        *(__half2*)&g_woh[id + 2] = __floats2half2_rn(a.z, a.w);
        return;
    }

    int bg = blockIdx.x;
    int b = bg / GROUPS, g = bg % GROUPS;
    const float* xp = x + ((size_t)b * C + g * CPG) * HW;
    const int NE = CPG * HW;

    float s = 0.f, ss = 0.f;
    for (int i = tid * 4; i < NE; i += 1024 * 4) {
        float4 v = *(const float4*)(xp + i);
        s += v.x + v.y + v.z + v.w;
        ss += v.x * v.x + v.y * v.y + v.z * v.z + v.w * v.w;
    }
    __shared__ float sbuf[32], ssbuf[32];
#pragma unroll
    for (int o = 16; o; o >>= 1) {
        s += __shfl_xor_sync(~0u, s, o);
        ss += __shfl_xor_sync(~0u, ss, o);
    }
    int w = tid >> 5;
    if ((tid & 31) == 0) { sbuf[w] = s; ssbuf[w] = ss; }
    __syncthreads();
    if (tid < 32) {
        s = sbuf[tid];
        ss = ssbuf[tid];
#pragma unroll
        for (int o = 16; o; o >>= 1) {
            s += __shfl_xor_sync(~0u, s, o);
            ss += __shfl_xor_sync(~0u, ss, o);
        }
        if (tid == 0) { sbuf[0] = s; ssbuf[0] = ss; }
    }
    __syncthreads();
    float mean = sbuf[0] / NE;
    float var = ssbuf[0] / NE - mean * mean;
    float rstd = rsqrtf(var + EPS);

    if (tid < CPG) {
        int c = g * CPG + tid;
        float ga = gamma[c] * rstd;
        g_scale[b * C + c] = ga;
        g_bias[b * C + c] = beta[c] - mean * ga;
    }
}

// ---------------------------------------------------------------------------
// 1b. GroupNorm apply + transpose, n-tiled for coalesced writes.
//     CTA = (32-n block, b), 256 threads. Reads x rows (L2-hot), writes
//     g_xh[n][0..511] as contiguous 1KB rows via a 32x520 fp16 smem tile.
// ---------------------------------------------------------------------------
#define AP_PITCH 520

__global__ void __launch_bounds__(256) gn_apply_kernel(const float* __restrict__ x) {
    __shared__ __half tile[32 * AP_PITCH];
    __shared__ float sga[C], sbe[C];
    const int b = blockIdx.y;
    const int n0 = blockIdx.x * 32;
    const int tid = threadIdx.x;

    // preload all 512 scale/bias
    {
        int i = tid * 2;
        *(float2*)&sga[i] = *(const float2*)&g_scale[b * C + i];
        *(float2*)&sbe[i] = *(const float2*)&g_bias[b * C + i];
    }
    __syncthreads();

    // load + normalize + transpose into smem: thread covers c-rows tid>>3 (+32..)
    const int cr0 = tid >> 3, n4 = (tid & 7) * 4;
    const float* xb = x + (size_t)b * C * HW + n0 + n4;
#pragma unroll
    for (int it = 0; it < 16; it++) {
        int c = cr0 + it * 32;
        float ga = sga[c], be = sbe[c];
        float4 v = *(const float4*)(xb + (size_t)c * HW);
        tile[(n4 + 0) * AP_PITCH + c] = __float2half(v.x * ga + be);
        tile[(n4 + 1) * AP_PITCH + c] = __float2half(v.y * ga + be);
        tile[(n4 + 2) * AP_PITCH + c] = __float2half(v.z * ga + be);
        tile[(n4 + 3) * AP_PITCH + c] = __float2half(v.w * ga + be);
    }
    __syncthreads();

    // write out: 4 n-rows per sweep, contiguous 1KB per row
    __half* ob = g_xh + ((size_t)b * HW + n0) * C;
#pragma unroll
    for (int it = 0; it < 8; it++) {
        int idx = tid + it * 256;
        int n = idx >> 6, cc = (idx & 63) * 8;
        *(uint4*)(ob + (size_t)n * C + cc) = *(const uint4*)&tile[n * AP_PITCH + cc];
    }
}

// ---------------------------------------------------------------------------
// 2. Fused QKV projection via fp16 MMA (R11/R14 best).
// ---------------------------------------------------------------------------
#define PJ_XT 0
#define PJ_XBUF 18432
#define PJ_WT 36864
#define PJ_WBUF 27648
#define PROJ_SMEM 92160

__global__ void __launch_bounds__(384, 1) proj_kernel(
        const float* __restrict__ bq, const float* __restrict__ bk,
        const float* __restrict__ bv) {
    extern __shared__ char smem[];
    const uint32_t sb = smem_u32(smem);
    const int tid = threadIdx.x, wid = tid >> 5, lane = tid & 31;
    const int g = lane >> 2, t = lane & 3;
    const int o = wid >> 2, mt = wid & 3;
    const int b = blockIdx.y;
    const int n0 = blockIdx.x * 128;
    const __half* xb = g_xh + (size_t)(b * HW + n0) * C;

    for (int i = tid; i < 1024; i += 384) {
        int r = i >> 3, ch = i & 7;
        cp16(sb + PJ_XT + r * 144 + ch * 16, xb + (size_t)r * C + ch * 8);
    }
    for (int i = tid; i < 1536; i += 384) {
        int r = i >> 3, ch = i & 7;
        const __half* wsrc = (r < 64) ? g_wqh : (r < 128) ? g_wkh : g_wvh;
        int rr = r & 63;
        cp16(sb + PJ_WT + r * 144 + ch * 16, wsrc + rr * C + ch * 8);
    }
    cp_commit();
    cp_wait0();
    __syncthreads();

    float acc[2][8][4];
#pragma unroll
    for (int s = 0; s < 2; s++)
#pragma unroll
        for (int j = 0; j < 8; j++)
#pragma unroll
            for (int k = 0; k < 4; k++) acc[s][j][k] = 0.f;

    const uint32_t lmrow = (lane & 7), lmcol = (lane >> 3);

    for (int kc = 0; kc < 8; kc++) {
        int buf = kc & 1;
        if (kc < 7) {
            int k1 = (kc + 1) * 64;
            int nb = buf ^ 1;
            for (int i = tid; i < 1024; i += 384) {
                int r = i >> 3, ch = i & 7;
                cp16(sb + PJ_XT + nb * PJ_XBUF + r * 144 + ch * 16,
                     xb + (size_t)r * C + k1 + ch * 8);
            }
            for (int i = tid; i < 1536; i += 384) {
                int r = i >> 3, ch = i & 7;
                const __half* wsrc = (r < 64) ? g_wqh : (r < 128) ? g_wkh : g_wvh;
                int rr = r & 63;
                cp16(sb + PJ_WT + nb * PJ_WBUF + r * 144 + ch * 16,
                     wsrc + rr * C + k1 + ch * 8);
            }
        }
        cp_commit();

        uint32_t qa[2][4][4];
#pragma unroll
        for (int s = 0; s < 2; s++) {
            const char* ab = smem + PJ_XT + buf * PJ_XBUF +
                             (mt * 32 + s * 16 + g) * 144 + t * 4;
#pragma unroll
            for (int ks = 0; ks < 4; ks++) {
                qa[s][ks][0] = *(const uint32_t*)(ab + ks * 32);
                qa[s][ks][1] = *(const uint32_t*)(ab + 8 * 144 + ks * 32);
                qa[s][ks][2] = *(const uint32_t*)(ab + ks * 32 + 16);
                qa[s][ks][3] = *(const uint32_t*)(ab + 8 * 144 + ks * 32 + 16);
            }
        }
        uint32_t wbase = sb + PJ_WT + buf * PJ_WBUF + o * 64 * 144 +
                         lmrow * 144 + lmcol * 16;
#pragma unroll
        for (int j = 0; j < 8; j++) {
            uint32_t m0, m1, m2, m3, m4, m5, m6, m7;
            ldsm4(m0, m1, m2, m3, wbase + j * 8 * 144);
            ldsm4(m4, m5, m6, m7, wbase + j * 8 * 144 + 64);
#pragma unroll
            for (int s = 0; s < 2; s++) {
                mma_f16(acc[s][j][0], acc[s][j][1], acc[s][j][2], acc[s][j][3],
                        qa[s][0][0], qa[s][0][1], qa[s][0][2], qa[s][0][3], m0, m1,
                        acc[s][j][0], acc[s][j][1], acc[s][j][2], acc[s][j][3]);
                mma_f16(acc[s][j][0], acc[s][j][1], acc[s][j][2], acc[s][j][3],
                        qa[s][1][0], qa[s][1][1], qa[s][1][2], qa[s][1][3], m2, m3,
                        acc[s][j][0], acc[s][j][1], acc[s][j][2], acc[s][j][3]);
                mma_f16(acc[s][j][0], acc[s][j][1], acc[s][j][2], acc[s][j][3],
                        qa[s][2][0], qa[s][2][1], qa[s][2][2], qa[s][2][3], m4, m5,
                        acc[s][j][0], acc[s][j][1], acc[s][j][2], acc[s][j][3]);
                mma_f16(acc[s][j][0], acc[s][j][1], acc[s][j][2], acc[s][j][3],
                        qa[s][3][0], qa[s][3][1], qa[s][3][2], qa[s][3][3], m6, m7,
                        acc[s][j][0], acc[s][j][1], acc[s][j][2], acc[s][j][3]);
            }
        }
        if (kc < 7) {
            cp_wait0();
            __syncthreads();
        }
    }

    const float QSC = 0.125f * 1.44269504f;
    if (o == 0) {
        __half* outp = g_qh + (size_t)(b * HW + n0) * D;
#pragma unroll
        for (int s = 0; s < 2; s++) {
            int nloc = mt * 32 + s * 16 + g;
#pragma unroll
            for (int j = 0; j < 8; j++) {
                int d0 = 8 * j + 2 * t;
                float b0v = bq[d0], b1v = bq[d0 + 1];
                *(uint32_t*)&outp[(size_t)nloc * D + d0] =
                    packh2((acc[s][j][0] + b0v) * QSC, (acc[s][j][1] + b1v) * QSC);
                *(uint32_t*)&outp[(size_t)(nloc + 8) * D + d0] =
                    packh2((acc[s][j][2] + b0v) * QSC, (acc[s][j][3] + b1v) * QSC);
            }
        }
    } else if (o == 1) {
        __half* outp = g_kh + (size_t)(b * HW + n0) * D;
#pragma unroll
        for (int s = 0; s < 2; s++) {
            int nloc = mt * 32 + s * 16 + g;
#pragma unroll
            for (int j = 0; j < 8; j++) {
                int d0 = 8 * j + 2 * t;
                float b0v = bk[d0], b1v = bk[d0 + 1];
                *(uint32_t*)&outp[(size_t)nloc * D + d0] =
                    packh2(acc[s][j][0] + b0v, acc[s][j][1] + b1v);
                *(uint32_t*)&outp[(size_t)(nloc + 8) * D + d0] =
                    packh2(acc[s][j][2] + b0v, acc[s][j][3] + b1v);
            }
        }
    }
    __syncthreads();
    __half* vst = (__half*)smem;  // [64][136]
    if (o == 2) {
#pragma unroll
        for (int s = 0; s < 2; s++) {
            int nloc = mt * 32 + s * 16 + g;
#pragma unroll
            for (int j = 0; j < 8; j++) {
                int d0 = 8 * j + 2 * t;
                float b0v = bv[d0], b1v = bv[d0 + 1];
                vst[d0 * 136 + nloc] = __float2half(acc[s][j][0] + b0v);
                vst[(d0 + 1) * 136 + nloc] = __float2half(acc[s][j][1] + b1v);
                vst[d0 * 136 + nloc + 8] = __float2half(acc[s][j][2] + b0v);
                vst[(d0 + 1) * 136 + nloc + 8] = __float2half(acc[s][j][3] + b1v);
            }
        }
    }
    __syncthreads();
    for (int i = tid; i < 1024; i += 384) {
        int d = i >> 4, nn = (i & 15) * 8;
        *(uint4*)&g_vth[((size_t)b * D + d) * HW + n0 + nn] =
            *(const uint4*)&vst[d * 136 + nn];
    }
}

// ---------------------------------------------------------------------------
// 3. Flash attention (R14 best): 128-query CTAs, 256 threads / 8 warps,
//    warp = m32 x key-half; cross-group O reduce; fused outproj + residual.
// ---------------------------------------------------------------------------
#define QPITCH 144
#define KPITCH 144
#define VPITCH 272
#define SQ_OFF 0
#define SK_OFF 18432
#define KBYTES 18432
#define SV_OFF (18432 + 2 * 18432)        // 55296
#define VBYTES (72 * 272)                 // 19584
#define ATTN_SMEM (SV_OFF + 2 * VBYTES)   // 94464

__global__ void __launch_bounds__(256, 1) attn_kernel(
        const float* __restrict__ x,
        const float* __restrict__ bo,
        float* __restrict__ out) {
    extern __shared__ char smem[];
    const uint32_t sb = smem_u32(smem);
    const int tid = threadIdx.x, wid = tid >> 5, lane = tid & 31;
    const int g = lane >> 2, t = lane & 3;
    const int mt = wid & 3, grp = wid >> 2;
    const int b = blockIdx.y;
    const int n0 = blockIdx.x * 128;

    const __half* qh = g_qh + ((size_t)b * HW + n0) * D;
    const __half* kh = g_kh + (size_t)b * HW * D;
    const __half* vh = g_vth + (size_t)b * D * HW;

    for (int i = tid; i < 1024; i += 256) {
        int r = i >> 3, ch = i & 7;
        cp16(sb + SQ_OFF + r * QPITCH + ch * 16, qh + r * 64 + ch * 8);
    }
    for (int i = tid; i < 1024; i += 256) {
        int r = i >> 3, ch = i & 7;
        cp16(sb + SK_OFF + r * KPITCH + ch * 16, kh + (size_t)r * 64 + ch * 8);
    }
    for (int i = tid; i < 1024; i += 256) {
        int r = i >> 4, ch = i & 15;
        cp16(sb + SV_OFF + r * VPITCH + ch * 16, vh + (size_t)r * HW + ch * 8);
    }
    cp_commit();
    for (int i = tid; i < 2 * 8 * 136; i += 256) {
        int bf = i / 1088, rem = i % 1088;
        int row = 64 + rem / 136, col = rem % 136;
        __half val = (row == 64 && col < 128) ? __float2half(1.f) : __float2half(0.f);
        *(__half*)(smem + SV_OFF + bf * VBYTES + row * VPITCH + col * 2) = val;
    }
    cp_wait0();
    __syncthreads();

    uint32_t qa[2][4][4];
#pragma unroll
    for (int s = 0; s < 2; s++) {
        const char* qbase = smem + SQ_OFF + (mt * 32 + s * 16 + g) * QPITCH + t * 4;
#pragma unroll
        for (int ks = 0; ks < 4; ks++) {
            qa[s][ks][0] = *(const uint32_t*)(qbase + ks * 32);
            qa[s][ks][1] = *(const uint32_t*)(qbase + 8 * QPITCH + ks * 32);
            qa[s][ks][2] = *(const uint32_t*)(qbase + ks * 32 + 16);
            qa[s][ks][3] = *(const uint32_t*)(qbase + 8 * QPITCH + ks * 32 + 16);
        }
    }

    float o[2][9][4];
#pragma unroll
    for (int s = 0; s < 2; s++)
#pragma unroll
        for (int j = 0; j < 9; j++)
#pragma unroll
            for (int k = 0; k < 4; k++) o[s][j][k] = 0.f;

    const uint32_t lmrow = (lane & 7), lmcol = (lane >> 3);

    for (int it = 0; it < 32; it++) {
        int buf = it & 1;

        if (it + 1 < 32) {
            int t1 = (it + 1) * 128;
            int nb = buf ^ 1;
            for (int i = tid; i < 1024; i += 256) {
                int r = i >> 3, ch = i & 7;
                cp16(sb + SK_OFF + nb * KBYTES + r * KPITCH + ch * 16,
                     kh + (size_t)(t1 + r) * 64 + ch * 8);
            }
            for (int i = tid; i < 1024; i += 256) {
                int r = i >> 4, ch = i & 15;
                cp16(sb + SV_OFF + nb * VBYTES + r * VPITCH + ch * 16,
                     vh + (size_t)r * HW + t1 + ch * 8);
            }
        }
        cp_commit();

        uint32_t kaddr = sb + SK_OFF + buf * KBYTES +
                         (grp * 64 + lmrow) * KPITCH + lmcol * 16;
        uint32_t vaddr = sb + SV_OFF + buf * VBYTES + lmrow * VPITCH + lmcol * 16;

        uint32_t pa[2][4][4];
#pragma unroll
        for (int j = 0; j < 8; j++) {
            uint32_t kj = kaddr + j * 8 * KPITCH;
            uint32_t m0, m1, m2, m3, m4, m5, m6, m7;
            ldsm4(m0, m1, m2, m3, kj);
            ldsm4(m4, m5, m6, m7, kj + 64);
#pragma unroll
            for (int s = 0; s < 2; s++) {
                uint32_t d0 = 0, d1 = 0;
                mma_f16h(d0, d1, qa[s][0][0], qa[s][0][1], qa[s][0][2], qa[s][0][3], m0, m1);
                mma_f16h(d0, d1, qa[s][1][0], qa[s][1][1], qa[s][1][2], qa[s][1][3], m2, m3);
                mma_f16h(d0, d1, qa[s][2][0], qa[s][2][1], qa[s][2][2], qa[s][2][3], m4, m5);
                mma_f16h(d0, d1, qa[s][3][0], qa[s][3][1], qa[s][3][2], qa[s][3][3], m6, m7);
                pa[s][j >> 1][(j & 1) * 2 + 0] = ex2h2(d0);
                pa[s][j >> 1][(j & 1) * 2 + 1] = ex2h2(d1);
            }
        }

#pragma unroll
        for (int j = 0; j < 9; j++) {
            uint32_t vj = vaddr + j * 8 * VPITCH;
#pragma unroll
            for (int h = 0; h < 2; h++) {
                uint32_t m0, m1, m2, m3;
                ldsm4(m0, m1, m2, m3, vj + (grp * 2 + h) * 64);
#pragma unroll
                for (int s = 0; s < 2; s++) {
                    mma_f16(o[s][j][0], o[s][j][1], o[s][j][2], o[s][j][3],
                            pa[s][2 * h][0], pa[s][2 * h][1], pa[s][2 * h][2], pa[s][2 * h][3],
                            m0, m1, o[s][j][0], o[s][j][1], o[s][j][2], o[s][j][3]);
                    mma_f16(o[s][j][0], o[s][j][1], o[s][j][2], o[s][j][3],
                            pa[s][2 * h + 1][0], pa[s][2 * h + 1][1], pa[s][2 * h + 1][2], pa[s][2 * h + 1][3],
                            m2, m3, o[s][j][0], o[s][j][1], o[s][j][2], o[s][j][3]);
                }
            }
        }

        if (it + 1 < 32) {
            cp_wait0();
            __syncthreads();
        }
    }

    // ---- cross-group O reduction ----
    __syncthreads();
    float* st = (float*)(smem + SK_OFF);   // [128][72] fp32
    if (grp == 1) {
#pragma unroll
        for (int s = 0; s < 2; s++) {
            int rb = mt * 32 + s * 16 + g;
#pragma unroll
            for (int j = 0; j < 9; j++) {
                int cl = 8 * j + 2 * t;
                st[rb * 72 + cl] = o[s][j][0];
                st[rb * 72 + cl + 1] = o[s][j][1];
                st[(rb + 8) * 72 + cl] = o[s][j][2];
                st[(rb + 8) * 72 + cl + 1] = o[s][j][3];
            }
        }
    }
    __syncthreads();
    if (grp == 0) {
#pragma unroll
        for (int s = 0; s < 2; s++) {
            int rb = mt * 32 + s * 16 + g;
#pragma unroll
            for (int j = 0; j < 9; j++) {
                int cl = 8 * j + 2 * t;
                o[s][j][0] += st[rb * 72 + cl];
                o[s][j][1] += st[rb * 72 + cl + 1];
                o[s][j][2] += st[(rb + 8) * 72 + cl];
                o[s][j][3] += st[(rb + 8) * 72 + cl + 1];
            }
        }
        float i0[2], i1[2];
#pragma unroll
        for (int s = 0; s < 2; s++) {
            float l0 = __shfl_sync(~0u, o[s][8][0], lane & 28);
            float l1 = __shfl_sync(~0u, o[s][8][2], lane & 28);
            i0[s] = 1.f / l0;
            i1[s] = 1.f / l1;
        }
        char* aos = smem + SQ_OFF;
#pragma unroll
        for (int s = 0; s < 2; s++) {
            int nloc = mt * 32 + s * 16 + g;
#pragma unroll
            for (int j = 0; j < 8; j++) {
                int d0 = 8 * j + 2 * t;
                *(uint32_t*)(aos + nloc * 144 + d0 * 2) =
                    packh2(o[s][j][0] * i0[s], o[s][j][1] * i0[s]);
                *(uint32_t*)(aos + (nloc + 8) * 144 + d0 * 2) =
                    packh2(o[s][j][2] * i1[s], o[s][j][3] * i1[s]);
            }
        }
    }
    __syncthreads();

    // ---- fused output projection ----
    for (int i = tid; i < 1024; i += 256) {
        int r = i >> 3, ch = i & 7;
        cp16(sb + SK_OFF + r * 144 + ch * 16, g_woh + (size_t)r * 64 + ch * 8);
    }
    cp_commit();
    cp_wait0();
    __syncthreads();

    for (int cc = 0; cc < 4; cc++) {
        int buf = cc & 1;
        if (cc < 3) {
            int cb1 = (cc + 1) * 128;
            int nb = buf ^ 1;
            for (int i = tid; i < 1024; i += 256) {
                int r = i >> 3, ch = i & 7;
                cp16(sb + SK_OFF + nb * KBYTES + r * 144 + ch * 16,
                     g_woh + (size_t)(cb1 + r) * 64 + ch * 8);
            }
        }
        cp_commit();

        const char* abase = smem + SK_OFF + buf * KBYTES + (wid * 16 + g) * 144 + t * 4;
        uint32_t wa[4][4];
#pragma unroll
        for (int ks = 0; ks < 4; ks++) {
            wa[ks][0] = *(const uint32_t*)(abase + ks * 32);
            wa[ks][1] = *(const uint32_t*)(abase + 8 * 144 + ks * 32);
            wa[ks][2] = *(const uint32_t*)(abase + ks * 32 + 16);
            wa[ks][3] = *(const uint32_t*)(abase + 8 * 144 + ks * 32 + 16);
        }
        uint32_t bb = sb + SQ_OFF + lmrow * 144 + lmcol * 16;

        int c_row = cc * 128 + wid * 16 + g;
        float bo0 = __ldg(&bo[c_row]);
        float bo1 = __ldg(&bo[c_row + 8]);
        const float* xr = x + ((size_t)b * C + c_row) * HW + n0;
        float* outr = out + ((size_t)b * C + c_row) * HW + n0;

#pragma unroll
        for (int j = 0; j < 16; j++) {
            uint32_t bj = bb + j * 8 * 144;
            uint32_t m0, m1, m2, m3, m4, m5, m6, m7;
            ldsm4(m0, m1, m2, m3, bj);
            ldsm4(m4, m5, m6, m7, bj + 64);
            float a0 = 0.f, a1 = 0.f, a2 = 0.f, a3 = 0.f;
            mma_f16(a0, a1, a2, a3, wa[0][0], wa[0][1], wa[0][2], wa[0][3],
                    m0, m1, a0, a1, a2, a3);
            mma_f16(a0, a1, a2, a3, wa[1][0], wa[1][1], wa[1][2], wa[1][3],
                    m2, m3, a0, a1, a2, a3);
            mma_f16(a0, a1, a2, a3, wa[2][0], wa[2][1], wa[2][2], wa[2][3],
                    m4, m5, a0, a1, a2, a3);
            mma_f16(a0, a1, a2, a3, wa[3][0], wa[3][1], wa[3][2], wa[3][3],
                    m6, m7, a0, a1, a2, a3);
            int nl = 8 * j + 2 * t;
            float2 xv0 = *(const float2*)(xr + nl);
            float2 xv1 = *(const float2*)(xr + 8 * HW + nl);
            float2 r0 = {a0 + bo0 + xv0.x, a1 + bo0 + xv0.y};
            float2 r1 = {a2 + bo1 + xv1.x, a3 + bo1 + xv1.y};
            *(float2*)(outr + nl) = r0;
            *(float2*)(outr + 8 * HW + nl) = r1;
        }

        if (cc < 3) {
            cp_wait0();
            __syncthreads();
        }
    }
}

// ---------------------------------------------------------------------------
extern "C" void kernel_launch(void* const* d_in, const int* in_sizes, int n_in,
                              void* d_out, int out_size) {
    const float* x     = (const float*)d_in[0];
    const float* gamma = (const float*)d_in[1];
    const float* beta  = (const float*)d_in[2];
    const float* wq    = (const float*)d_in[3];
    const float* bq    = (const float*)d_in[4];
    const float* wk    = (const float*)d_in[5];
    const float* bk    = (const float*)d_in[6];
    const float* wv    = (const float*)d_in[7];
    const float* bv    = (const float*)d_in[8];
    const float* wo    = (const float*)d_in[9];
    const float* bo    = (const float*)d_in[10];
    float* out = (float*)d_out;

    static int attr_done = 0;
    if (!attr_done) {
        cudaFuncSetAttribute(attn_kernel, cudaFuncAttributeMaxDynamicSharedMemorySize,
                             ATTN_SMEM);
        cudaFuncSetAttribute(proj_kernel, cudaFuncAttributeMaxDynamicSharedMemorySize,
                             PROJ_SMEM);
        attr_done = 1;
    }

    gn_stats_kernel<<<BB * GROUPS + 8, 1024>>>(x, gamma, beta, wq, wk, wv, wo);
    gn_apply_kernel<<<dim3(HW / 32, BB), 256>>>(x);
    proj_kernel<<<dim3(HW / 128, BB), 384, PROJ_SMEM>>>(bq, bk, bv);
    attn_kernel<<<dim3(HW / 128, BB), 256, ATTN_SMEM>>>(x, bo, out);
}

// round 16
// speedup vs baseline: 1.6078x; 1.6078x over previous
#include <cuda_runtime.h>
#include <cuda_fp16.h>
#include <cstdint>

#define BB 4
#define C 512
#define D 64
#define HW 4096
#define GROUPS 32
#define CPG 16
#define EPS 1e-5f

// Scratch (device globals — no allocation allowed)
__device__ __half g_xh[BB * HW * C];     // normalized x, transposed [B,N,C] fp16
__device__ __half g_wqh[D * C], g_wkh[D * C], g_wvh[D * C], g_woh[C * D];
__device__ __half g_qh[BB * HW * D];     // [B,N,D] fp16, pre-scaled by 0.125*log2e
__device__ __half g_kh[BB * HW * D];     // [B,N,D] fp16
__device__ __half g_vth[BB * D * HW];    // [B,D,N] fp16

// ---------------------------------------------------------------------------
// helpers
// ---------------------------------------------------------------------------
__device__ __forceinline__ uint32_t smem_u32(const void* p) {
    uint32_t a;
    asm("{ .reg .u64 t; cvta.to.shared.u64 t, %1; cvt.u32.u64 %0, t; }" : "=r"(a) : "l"(p));
    return a;
}
__device__ __forceinline__ void cp16(uint32_t s, const void* g) {
    asm volatile("cp.async.cg.shared.global [%0], [%1], 16;" :: "r"(s), "l"(g));
}
__device__ __forceinline__ void cp_commit() { asm volatile("cp.async.commit_group;"); }
__device__ __forceinline__ void cp_wait0() { asm volatile("cp.async.wait_group 0;" ::: "memory"); }

__device__ __forceinline__ void mma_f16(float& d0, float& d1, float& d2, float& d3,
                                        uint32_t a0, uint32_t a1, uint32_t a2, uint32_t a3,
                                        uint32_t b0, uint32_t b1,
                                        float c0, float c1, float c2, float c3) {
    asm volatile(
        "mma.sync.aligned.m16n8k16.row.col.f32.f16.f16.f32 "
        "{%0,%1,%2,%3},{%4,%5,%6,%7},{%8,%9},{%10,%11,%12,%13};"
        : "=f"(d0), "=f"(d1), "=f"(d2), "=f"(d3)
        : "r"(a0), "r"(a1), "r"(a2), "r"(a3), "r"(b0), "r"(b1),
          "f"(c0), "f"(c1), "f"(c2), "f"(c3));
}
__device__ __forceinline__ void mma_f16h(uint32_t& d0, uint32_t& d1,
                                         uint32_t a0, uint32_t a1, uint32_t a2, uint32_t a3,
                                         uint32_t b0, uint32_t b1) {
    asm volatile(
        "mma.sync.aligned.m16n8k16.row.col.f16.f16.f16.f16 "
        "{%0,%1},{%2,%3,%4,%5},{%6,%7},{%0,%1};"
        : "+r"(d0), "+r"(d1)
        : "r"(a0), "r"(a1), "r"(a2), "r"(a3), "r"(b0), "r"(b1));
}
__device__ __forceinline__ void ldsm4(uint32_t& r0, uint32_t& r1, uint32_t& r2, uint32_t& r3,
                                      uint32_t addr) {
    asm volatile("ldmatrix.sync.aligned.m8n8.x4.shared.b16 {%0,%1,%2,%3}, [%4];"
                 : "=r"(r0), "=r"(r1), "=r"(r2), "=r"(r3) : "r"(addr));
}
__device__ __forceinline__ uint32_t packh2(float lo, float hi) {
    __half2 h = __floats2half2_rn(lo, hi);
    return *(uint32_t*)&h;
}
__device__ __forceinline__ uint32_t ex2h2(uint32_t s) {
    uint32_t p;
    asm("ex2.approx.f16x2 %0, %1;" : "=r"(p) : "r"(s));
    return p;
}
__device__ __forceinline__ uint32_t haddh2(uint32_t a, uint32_t b) {
    uint32_t r;
    asm("add.rn.f16x2 %0, %1, %2;" : "=r"(r) : "r"(a), "r"(b));
    return r;
}

// ---------------------------------------------------------------------------
// 1. Fused GroupNorm (stats + apply + transpose) + weight convert (R11 best).
// ---------------------------------------------------------------------------
__global__ void __launch_bounds__(512) gn_fused_kernel(
        const float* __restrict__ x,
        const float* __restrict__ gamma, const float* __restrict__ beta,
        const float* __restrict__ wq, const float* __restrict__ wk,
        const float* __restrict__ wv, const float* __restrict__ wo) {
    int tid = threadIdx.x;
    if (blockIdx.x >= BB * GROUPS) {
        int id = ((blockIdx.x - BB * GROUPS) * 512 + tid) * 4;
        float4 a;
        a = *(const float4*)&wq[id];
        *(__half2*)&g_wqh[id] = __floats2half2_rn(a.x, a.y);
        *(__half2*)&g_wqh[id + 2] = __floats2half2_rn(a.z, a.w);
        a = *(const float4*)&wk[id];
        *(__half2*)&g_wkh[id] = __floats2half2_rn(a.x, a.y);
        *(__half2*)&g_wkh[id + 2] = __floats2half2_rn(a.z, a.w);
        a = *(const float4*)&wv[id];
        *(__half2*)&g_wvh[id] = __floats2half2_rn(a.x, a.y);
        *(__half2*)&g_wvh[id + 2] = __floats2half2_rn(a.z, a.w);
        a = *(const float4*)&wo[id];
        *(__half2*)&g_woh[id] = __floats2half2_rn(a.x, a.y);
        *(__half2*)&g_woh[id + 2] = __floats2half2_rn(a.z, a.w);
        return;
    }

    int bg = blockIdx.x;
    int b = bg / GROUPS, g = bg % GROUPS;
    const float* xp = x + ((size_t)b * C + g * CPG) * HW;
    const int NE = CPG * HW;

    float s = 0.f, ss = 0.f;
    for (int i = tid * 4; i < NE; i += 512 * 4) {
        float4 v = *(const float4*)(xp + i);
        s += v.x + v.y + v.z + v.w;
        ss += v.x * v.x + v.y * v.y + v.z * v.z + v.w * v.w;
    }
    __shared__ float sbuf[32], ssbuf[32];
    __shared__ float sga[CPG], sbe[CPG];
#pragma unroll
    for (int o = 16; o; o >>= 1) {
        s += __shfl_xor_sync(~0u, s, o);
        ss += __shfl_xor_sync(~0u, ss, o);
    }
    int w = tid >> 5;
    if ((tid & 31) == 0) { sbuf[w] = s; ssbuf[w] = ss; }
    __syncthreads();
    if (tid < 32) {
        s = tid < 16 ? sbuf[tid] : 0.f;
        ss = tid < 16 ? ssbuf[tid] : 0.f;
#pragma unroll
        for (int o = 8; o; o >>= 1) {
            s += __shfl_xor_sync(~0u, s, o);
            ss += __shfl_xor_sync(~0u, ss, o);
        }
        if (tid == 0) { sbuf[0] = s; ssbuf[0] = ss; }
    }
    __syncthreads();
    float mean = sbuf[0] / NE;
    float var = ssbuf[0] / NE - mean * mean;
    float rstd = rsqrtf(var + EPS);

    if (tid < CPG) {
        int c = g * CPG + tid;
        float ga = gamma[c] * rstd;
        sga[tid] = ga;
        sbe[tid] = beta[c] - mean * ga;
    }
    __syncthreads();

    float lga[CPG], lbe[CPG];
#pragma unroll
    for (int c = 0; c < CPG; c++) { lga[c] = sga[c]; lbe[c] = sbe[c]; }

    for (int n0i = tid * 4; n0i < HW; n0i += 512 * 4) {
        __align__(16) __half tmp[4][CPG];
#pragma unroll
        for (int c = 0; c < CPG; c++) {
            float4 v = *(const float4*)&xp[(size_t)c * HW + n0i];
            tmp[0][c] = __float2half(v.x * lga[c] + lbe[c]);
            tmp[1][c] = __float2half(v.y * lga[c] + lbe[c]);
            tmp[2][c] = __float2half(v.z * lga[c] + lbe[c]);
            tmp[3][c] = __float2half(v.w * lga[c] + lbe[c]);
        }
#pragma unroll
        for (int k = 0; k < 4; k++) {
            __half* dst = g_xh + ((size_t)b * HW + n0i + k) * C + g * CPG;
            ((uint4*)dst)[0] = ((const uint4*)tmp[k])[0];
            ((uint4*)dst)[1] = ((const uint4*)tmp[k])[1];
        }
    }
}

// ---------------------------------------------------------------------------
// 2. Fused QKV projection via fp16 MMA (R11/R14 best).
// ---------------------------------------------------------------------------
#define PJ_XT 0
#define PJ_XBUF 18432
#define PJ_WT 36864
#define PJ_WBUF 27648
#define PROJ_SMEM 92160

__global__ void __launch_bounds__(384, 1) proj_kernel(
        const float* __restrict__ bq, const float* __restrict__ bk,
        const float* __restrict__ bv) {
    extern __shared__ char smem[];
    const uint32_t sb = smem_u32(smem);
    const int tid = threadIdx.x, wid = tid >> 5, lane = tid & 31;
    const int g = lane >> 2, t = lane & 3;
    const int o = wid >> 2, mt = wid & 3;
    const int b = blockIdx.y;
    const int n0 = blockIdx.x * 128;
    const __half* xb = g_xh + (size_t)(b * HW + n0) * C;

    for (int i = tid; i < 1024; i += 384) {
        int r = i >> 3, ch = i & 7;
        cp16(sb + PJ_XT + r * 144 + ch * 16, xb + (size_t)r * C + ch * 8);
    }
    for (int i = tid; i < 1536; i += 384) {
        int r = i >> 3, ch = i & 7;
        const __half* wsrc = (r < 64) ? g_wqh : (r < 128) ? g_wkh : g_wvh;
        int rr = r & 63;
        cp16(sb + PJ_WT + r * 144 + ch * 16, wsrc + rr * C + ch * 8);
    }
    cp_commit();
    cp_wait0();
    __syncthreads();

    float acc[2][8][4];
#pragma unroll
    for (int s = 0; s < 2; s++)
#pragma unroll
        for (int j = 0; j < 8; j++)
#pragma unroll
            for (int k = 0; k < 4; k++) acc[s][j][k] = 0.f;

    const uint32_t lmrow = (lane & 7), lmcol = (lane >> 3);

    for (int kc = 0; kc < 8; kc++) {
        int buf = kc & 1;
        if (kc < 7) {
            int k1 = (kc + 1) * 64;
            int nb = buf ^ 1;
            for (int i = tid; i < 1024; i += 384) {
                int r = i >> 3, ch = i & 7;
                cp16(sb + PJ_XT + nb * PJ_XBUF + r * 144 + ch * 16,
                     xb + (size_t)r * C + k1 + ch * 8);
            }
            for (int i = tid; i < 1536; i += 384) {
                int r = i >> 3, ch = i & 7;
                const __half* wsrc = (r < 64) ? g_wqh : (r < 128) ? g_wkh : g_wvh;
                int rr = r & 63;
                cp16(sb + PJ_WT + nb * PJ_WBUF + r * 144 + ch * 16,
                     wsrc + rr * C + k1 + ch * 8);
            }
        }
        cp_commit();

        uint32_t qa[2][4][4];
#pragma unroll
        for (int s = 0; s < 2; s++) {
            const char* ab = smem + PJ_XT + buf * PJ_XBUF +
                             (mt * 32 + s * 16 + g) * 144 + t * 4;
#pragma unroll
            for (int ks = 0; ks < 4; ks++) {
                qa[s][ks][0] = *(const uint32_t*)(ab + ks * 32);
                qa[s][ks][1] = *(const uint32_t*)(ab + 8 * 144 + ks * 32);
                qa[s][ks][2] = *(const uint32_t*)(ab + ks * 32 + 16);
                qa[s][ks][3] = *(const uint32_t*)(ab + 8 * 144 + ks * 32 + 16);
            }
        }
        uint32_t wbase = sb + PJ_WT + buf * PJ_WBUF + o * 64 * 144 +
                         lmrow * 144 + lmcol * 16;
#pragma unroll
        for (int j = 0; j < 8; j++) {
            uint32_t m0, m1, m2, m3, m4, m5, m6, m7;
            ldsm4(m0, m1, m2, m3, wbase + j * 8 * 144);
            ldsm4(m4, m5, m6, m7, wbase + j * 8 * 144 + 64);
#pragma unroll
            for (int s = 0; s < 2; s++) {
                mma_f16(acc[s][j][0], acc[s][j][1], acc[s][j][2], acc[s][j][3],
                        qa[s][0][0], qa[s][0][1], qa[s][0][2], qa[s][0][3], m0, m1,
                        acc[s][j][0], acc[s][j][1], acc[s][j][2], acc[s][j][3]);
                mma_f16(acc[s][j][0], acc[s][j][1], acc[s][j][2], acc[s][j][3],
                        qa[s][1][0], qa[s][1][1], qa[s][1][2], qa[s][1][3], m2, m3,
                        acc[s][j][0], acc[s][j][1], acc[s][j][2], acc[s][j][3]);
                mma_f16(acc[s][j][0], acc[s][j][1], acc[s][j][2], acc[s][j][3],
                        qa[s][2][0], qa[s][2][1], qa[s][2][2], qa[s][2][3], m4, m5,
                        acc[s][j][0], acc[s][j][1], acc[s][j][2], acc[s][j][3]);
                mma_f16(acc[s][j][0], acc[s][j][1], acc[s][j][2], acc[s][j][3],
                        qa[s][3][0], qa[s][3][1], qa[s][3][2], qa[s][3][3], m6, m7,
                        acc[s][j][0], acc[s][j][1], acc[s][j][2], acc[s][j][3]);
            }
        }
        if (kc < 7) {
            cp_wait0();
            __syncthreads();
        }
    }

    const float QSC = 0.125f * 1.44269504f;
    if (o == 0) {
        __half* outp = g_qh + (size_t)(b * HW + n0) * D;
#pragma unroll
        for (int s = 0; s < 2; s++) {
            int nloc = mt * 32 + s * 16 + g;
#pragma unroll
            for (int j = 0; j < 8; j++) {
                int d0 = 8 * j + 2 * t;
                float b0v = bq[d0], b1v = bq[d0 + 1];
                *(uint32_t*)&outp[(size_t)nloc * D + d0] =
                    packh2((acc[s][j][0] + b0v) * QSC, (acc[s][j][1] + b1v) * QSC);
                *(uint32_t*)&outp[(size_t)(nloc + 8) * D + d0] =
                    packh2((acc[s][j][2] + b0v) * QSC, (acc[s][j][3] + b1v) * QSC);
            }
        }
    } else if (o == 1) {
        __half* outp = g_kh + (size_t)(b * HW + n0) * D;
#pragma unroll
        for (int s = 0; s < 2; s++) {
            int nloc = mt * 32 + s * 16 + g;
#pragma unroll
            for (int j = 0; j < 8; j++) {
                int d0 = 8 * j + 2 * t;
                float b0v = bk[d0], b1v = bk[d0 + 1];
                *(uint32_t*)&outp[(size_t)nloc * D + d0] =
                    packh2(acc[s][j][0] + b0v, acc[s][j][1] + b1v);
                *(uint32_t*)&outp[(size_t)(nloc + 8) * D + d0] =
                    packh2(acc[s][j][2] + b0v, acc[s][j][3] + b1v);
            }
        }
    }
    __syncthreads();
    __half* vst = (__half*)smem;  // [64][136]
    if (o == 2) {
#pragma unroll
        for (int s = 0; s < 2; s++) {
            int nloc = mt * 32 + s * 16 + g;
#pragma unroll
            for (int j = 0; j < 8; j++) {
                int d0 = 8 * j + 2 * t;
                float b0v = bv[d0], b1v = bv[d0 + 1];
                vst[d0 * 136 + nloc] = __float2half(acc[s][j][0] + b0v);
                vst[(d0 + 1) * 136 + nloc] = __float2half(acc[s][j][1] + b1v);
                vst[d0 * 136 + nloc + 8] = __float2half(acc[s][j][2] + b0v);
                vst[(d0 + 1) * 136 + nloc + 8] = __float2half(acc[s][j][3] + b1v);
            }
        }
    }
    __syncthreads();
    for (int i = tid; i < 1024; i += 384) {
        int d = i >> 4, nn = (i & 15) * 8;
        *(uint4*)&g_vth[((size_t)b * D + d) * HW + n0 + nn] =
            *(const uint4*)&vst[d * 136 + nn];
    }
}

// ---------------------------------------------------------------------------
// 3. Flash attention (R14): 128-query CTAs, 256 threads / 8 warps,
//    warp = m32 x key-half; dual-chain QK (halved MMA dependency depth);
//    cross-group O reduce; fused outproj + residual.
// ---------------------------------------------------------------------------
#define QPITCH 144
#define KPITCH 144
#define VPITCH 272
#define SQ_OFF 0
#define SK_OFF 18432
#define KBYTES 18432
#define SV_OFF (18432 + 2 * 18432)        // 55296
#define VBYTES (72 * 272)                 // 19584
#define ATTN_SMEM (SV_OFF + 2 * VBYTES)   // 94464

__global__ void __launch_bounds__(256, 1) attn_kernel(
        const float* __restrict__ x,
        const float* __restrict__ bo,
        float* __restrict__ out) {
    extern __shared__ char smem[];
    const uint32_t sb = smem_u32(smem);
    const int tid = threadIdx.x, wid = tid >> 5, lane = tid & 31;
    const int g = lane >> 2, t = lane & 3;
    const int mt = wid & 3, grp = wid >> 2;
    const int b = blockIdx.y;
    const int n0 = blockIdx.x * 128;

    const __half* qh = g_qh + ((size_t)b * HW + n0) * D;
    const __half* kh = g_kh + (size_t)b * HW * D;
    const __half* vh = g_vth + (size_t)b * D * HW;

    for (int i = tid; i < 1024; i += 256) {
        int r = i >> 3, ch = i & 7;
        cp16(sb + SQ_OFF + r * QPITCH + ch * 16, qh + r * 64 + ch * 8);
    }
    for (int i = tid; i < 1024; i += 256) {
        int r = i >> 3, ch = i & 7;
        cp16(sb + SK_OFF + r * KPITCH + ch * 16, kh + (size_t)r * 64 + ch * 8);
    }
    for (int i = tid; i < 1024; i += 256) {
        int r = i >> 4, ch = i & 15;
        cp16(sb + SV_OFF + r * VPITCH + ch * 16, vh + (size_t)r * HW + ch * 8);
    }
    cp_commit();
    for (int i = tid; i < 2 * 8 * 136; i += 256) {
        int bf = i / 1088, rem = i % 1088;
        int row = 64 + rem / 136, col = rem % 136;
        __half val = (row == 64 && col < 128) ? __float2half(1.f) : __float2half(0.f);
        *(__half*)(smem + SV_OFF + bf * VBYTES + row * VPITCH + col * 2) = val;
    }
    cp_wait0();
    __syncthreads();

    uint32_t qa[2][4][4];
#pragma unroll
    for (int s = 0; s < 2; s++) {
        const char* qbase = smem + SQ_OFF + (mt * 32 + s * 16 + g) * QPITCH + t * 4;
#pragma unroll
        for (int ks = 0; ks < 4; ks++) {
            qa[s][ks][0] = *(const uint32_t*)(qbase + ks * 32);
            qa[s][ks][1] = *(const uint32_t*)(qbase + 8 * QPITCH + ks * 32);
            qa[s][ks][2] = *(const uint32_t*)(qbase + ks * 32 + 16);
            qa[s][ks][3] = *(const uint32_t*)(qbase + 8 * QPITCH + ks * 32 + 16);
        }
    }

    float o[2][9][4];
#pragma unroll
    for (int s = 0; s < 2; s++)
#pragma unroll
        for (int j = 0; j < 9; j++)
#pragma unroll
            for (int k = 0; k < 4; k++) o[s][j][k] = 0.f;

    const uint32_t lmrow = (lane & 7), lmcol = (lane >> 3);

    for (int it = 0; it < 32; it++) {
        int buf = it & 1;

        if (it + 1 < 32) {
            int t1 = (it + 1) * 128;
            int nb = buf ^ 1;
            for (int i = tid; i < 1024; i += 256) {
                int r = i >> 3, ch = i & 7;
                cp16(sb + SK_OFF + nb * KBYTES + r * KPITCH + ch * 16,
                     kh + (size_t)(t1 + r) * 64 + ch * 8);
            }
            for (int i = tid; i < 1024; i += 256) {
                int r = i >> 4, ch = i & 15;
                cp16(sb + SV_OFF + nb * VBYTES + r * VPITCH + ch * 16,
                     vh + (size_t)r * HW + t1 + ch * 8);
            }
        }
        cp_commit();

        uint32_t kaddr = sb + SK_OFF + buf * KBYTES +
                         (grp * 64 + lmrow) * KPITCH + lmcol * 16;
        uint32_t vaddr = sb + SV_OFF + buf * VBYTES + lmrow * VPITCH + lmcol * 16;

        uint32_t pa[2][4][4];
#pragma unroll
        for (int j = 0; j < 8; j++) {
            uint32_t kj = kaddr + j * 8 * KPITCH;
            uint32_t m0, m1, m2, m3, m4, m5, m6, m7;
            ldsm4(m0, m1, m2, m3, kj);
            ldsm4(m4, m5, m6, m7, kj + 64);
#pragma unroll
            for (int s = 0; s < 2; s++) {
                uint32_t d0 = 0, d1 = 0, e0 = 0, e1 = 0;   // two independent chains
                mma_f16h(d0, d1, qa[s][0][0], qa[s][0][1], qa[s][0][2], qa[s][0][3], m0, m1);
                mma_f16h(e0, e1, qa[s][1][0], qa[s][1][1], qa[s][1][2], qa[s][1][3], m2, m3);
                mma_f16h(d0, d1, qa[s][2][0], qa[s][2][1], qa[s][2][2], qa[s][2][3], m4, m5);
                mma_f16h(e0, e1, qa[s][3][0], qa[s][3][1], qa[s][3][2], qa[s][3][3], m6, m7);
                d0 = haddh2(d0, e0);
                d1 = haddh2(d1, e1);
                pa[s][j >> 1][(j & 1) * 2 + 0] = ex2h2(d0);
                pa[s][j >> 1][(j & 1) * 2 + 1] = ex2h2(d1);
            }
        }

#pragma unroll
        for (int j = 0; j < 9; j++) {
            uint32_t vj = vaddr + j * 8 * VPITCH;
#pragma unroll
            for (int h = 0; h < 2; h++) {
                uint32_t m0, m1, m2, m3;
                ldsm4(m0, m1, m2, m3, vj + (grp * 2 + h) * 64);
#pragma unroll
                for (int s = 0; s < 2; s++) {
                    mma_f16(o[s][j][0], o[s][j][1], o[s][j][2], o[s][j][3],
                            pa[s][2 * h][0], pa[s][2 * h][1], pa[s][2 * h][2], pa[s][2 * h][3],
                            m0, m1, o[s][j][0], o[s][j][1], o[s][j][2], o[s][j][3]);
                    mma_f16(o[s][j][0], o[s][j][1], o[s][j][2], o[s][j][3],
                            pa[s][2 * h + 1][0], pa[s][2 * h + 1][1], pa[s][2 * h + 1][2], pa[s][2 * h + 1][3],
                            m2, m3, o[s][j][0], o[s][j][1], o[s][j][2], o[s][j][3]);
                }
            }
        }

        if (it + 1 < 32) {
            cp_wait0();
            __syncthreads();
        }
    }

    // ---- cross-group O reduction ----
    __syncthreads();
    float* st = (float*)(smem + SK_OFF);   // [128][72] fp32
    if (grp == 1) {
#pragma unroll
        for (int s = 0; s < 2; s++) {
            int rb = mt * 32 + s * 16 + g;
#pragma unroll
            for (int j = 0; j < 9; j++) {
                int cl = 8 * j + 2 * t;
                st[rb * 72 + cl] = o[s][j][0];
                st[rb * 72 + cl + 1] = o[s][j][1];
                st[(rb + 8) * 72 + cl] = o[s][j][2];
                st[(rb + 8) * 72 + cl + 1] = o[s][j][3];
            }
        }
    }
    __syncthreads();
    if (grp == 0) {
#pragma unroll
        for (int s = 0; s < 2; s++) {
            int rb = mt * 32 + s * 16 + g;
#pragma unroll
            for (int j = 0; j < 9; j++) {
                int cl = 8 * j + 2 * t;
                o[s][j][0] += st[rb * 72 + cl];
                o[s][j][1] += st[rb * 72 + cl + 1];
                o[s][j][2] += st[(rb + 8) * 72 + cl];
                o[s][j][3] += st[(rb + 8) * 72 + cl + 1];
            }
        }
        float i0[2], i1[2];
#pragma unroll
        for (int s = 0; s < 2; s++) {
            float l0 = __shfl_sync(~0u, o[s][8][0], lane & 28);
            float l1 = __shfl_sync(~0u, o[s][8][2], lane & 28);
            i0[s] = 1.f / l0;
            i1[s] = 1.f / l1;
        }
        char* aos = smem + SQ_OFF;
#pragma unroll
        for (int s = 0; s < 2; s++) {
            int nloc = mt * 32 + s * 16 + g;
#pragma unroll
            for (int j = 0; j < 8; j++) {
                int d0 = 8 * j + 2 * t;
                *(uint32_t*)(aos + nloc * 144 + d0 * 2) =
                    packh2(o[s][j][0] * i0[s], o[s][j][1] * i0[s]);
                *(uint32_t*)(aos + (nloc + 8) * 144 + d0 * 2) =
                    packh2(o[s][j][2] * i1[s], o[s][j][3] * i1[s]);
            }
        }
    }
    __syncthreads();

    // ---- fused output projection ----
    for (int i = tid; i < 1024; i += 256) {
        int r = i >> 3, ch = i & 7;
        cp16(sb + SK_OFF + r * 144 + ch * 16, g_woh + (size_t)r * 64 + ch * 8);
    }
    cp_commit();
    cp_wait0();
    __syncthreads();

    for (int cc = 0; cc < 4; cc++) {
        int buf = cc & 1;
        if (cc < 3) {
            int cb1 = (cc + 1) * 128;
            int nb = buf ^ 1;
            for (int i = tid; i < 1024; i += 256) {
                int r = i >> 3, ch = i & 7;
                cp16(sb + SK_OFF + nb * KBYTES + r * 144 + ch * 16,
                     g_woh + (size_t)(cb1 + r) * 64 + ch * 8);
            }
        }
        cp_commit();

        const char* abase = smem + SK_OFF + buf * KBYTES + (wid * 16 + g) * 144 + t * 4;
        uint32_t wa[4][4];
#pragma unroll
        for (int ks = 0; ks < 4; ks++) {
            wa[ks][0] = *(const uint32_t*)(abase + ks * 32);
            wa[ks][1] = *(const uint32_t*)(abase + 8 * 144 + ks * 32);
            wa[ks][2] = *(const uint32_t*)(abase + ks * 32 + 16);
            wa[ks][3] = *(const uint32_t*)(abase + 8 * 144 + ks * 32 + 16);
        }
        uint32_t bb = sb + SQ_OFF + lmrow * 144 + lmcol * 16;

        int c_row = cc * 128 + wid * 16 + g;
        float bo0 = __ldg(&bo[c_row]);
        float bo1 = __ldg(&bo[c_row + 8]);
        const float* xr = x + ((size_t)b * C + c_row) * HW + n0;
        float* outr = out + ((size_t)b * C + c_row) * HW + n0;

#pragma unroll
        for (int j = 0; j < 16; j++) {
            uint32_t bj = bb + j * 8 * 144;
            uint32_t m0, m1, m2, m3, m4, m5, m6, m7;
            ldsm4(m0, m1, m2, m3, bj);
            ldsm4(m4, m5, m6, m7, bj + 64);
            float a0 = 0.f, a1 = 0.f, a2 = 0.f, a3 = 0.f;
            mma_f16(a0, a1, a2, a3, wa[0][0], wa[0][1], wa[0][2], wa[0][3],
                    m0, m1, a0, a1, a2, a3);
            mma_f16(a0, a1, a2, a3, wa[1][0], wa[1][1], wa[1][2], wa[1][3],
                    m2, m3, a0, a1, a2, a3);
            mma_f16(a0, a1, a2, a3, wa[2][0], wa[2][1], wa[2][2], wa[2][3],
                    m4, m5, a0, a1, a2, a3);
            mma_f16(a0, a1, a2, a3, wa[3][0], wa[3][1], wa[3][2], wa[3][3],
                    m6, m7, a0, a1, a2, a3);
            int nl = 8 * j + 2 * t;
            float2 xv0 = *(const float2*)(xr + nl);
            float2 xv1 = *(const float2*)(xr + 8 * HW + nl);
            float2 r0 = {a0 + bo0 + xv0.x, a1 + bo0 + xv0.y};
            float2 r1 = {a2 + bo1 + xv1.x, a3 + bo1 + xv1.y};
            *(float2*)(outr + nl) = r0;
            *(float2*)(outr + 8 * HW + nl) = r1;
        }

        if (cc < 3) {
            cp_wait0();
            __syncthreads();
        }
    }
}

// ---------------------------------------------------------------------------
extern "C" void kernel_launch(void* const* d_in, const int* in_sizes, int n_in,
                              void* d_out, int out_size) {
    const float* x     = (const float*)d_in[0];
    const float* gamma = (const float*)d_in[1];
    const float* beta  = (const float*)d_in[2];
    const float* wq    = (const float*)d_in[3];
    const float* bq    = (const float*)d_in[4];
    const float* wk    = (const float*)d_in[5];
    const float* bk    = (const float*)d_in[6];
    const float* wv    = (const float*)d_in[7];
    const float* bv    = (const float*)d_in[8];
    const float* wo    = (const float*)d_in[9];
    const float* bo    = (const float*)d_in[10];
    float* out = (float*)d_out;

    static int attr_done = 0;
    if (!attr_done) {
        cudaFuncSetAttribute(attn_kernel, cudaFuncAttributeMaxDynamicSharedMemorySize,
                             ATTN_SMEM);
        cudaFuncSetAttribute(proj_kernel, cudaFuncAttributeMaxDynamicSharedMemorySize,
                             PROJ_SMEM);
        attr_done = 1;
    }

    gn_fused_kernel<<<BB * GROUPS + 16, 512>>>(x, gamma, beta, wq, wk, wv, wo);
    proj_kernel<<<dim3(HW / 128, BB), 384, PROJ_SMEM>>>(bq, bk, bv);
    attn_kernel<<<dim3(HW / 128, BB), 256, ATTN_SMEM>>>(x, bo, out);
}